// round 6
// baseline (speedup 1.0000x reference)
#include <cuda_runtime.h>
#include <math.h>

#define N_PTS 8192
#define M_PTS 2048
#define K_LAST 10
#define VARS 3

typedef unsigned long long u64;

// ---------------- packed f32x2 helpers (sm_100+) ----------------
__device__ __forceinline__ u64 pk2(float lo, float hi) {
    u64 r; asm("mov.b64 %0,{%1,%2};" : "=l"(r) : "f"(lo), "f"(hi)); return r;
}
__device__ __forceinline__ u64 dup2(float x) { return pk2(x, x); }
__device__ __forceinline__ void unpk2(u64 v, float& lo, float& hi) {
    asm("mov.b64 {%0,%1},%2;" : "=f"(lo), "=f"(hi) : "l"(v));
}
__device__ __forceinline__ u64 f2fma(u64 a, u64 b, u64 c) {
    u64 d; asm("fma.rn.f32x2 %0,%1,%2,%3;" : "=l"(d) : "l"(a), "l"(b), "l"(c)); return d;
}
__device__ __forceinline__ u64 f2mul(u64 a, u64 b) {
    u64 d; asm("mul.rn.f32x2 %0,%1,%2;" : "=l"(d) : "l"(a), "l"(b)); return d;
}

// scalar exact GELU for proj kernel
__device__ __forceinline__ float gelu(float x) {
    return 0.5f * x * (1.0f + erff(x * 0.70710678118654752f));
}

// packed GELU via Abramowitz-Stegun 7.1.26 erf (abs err <= 1.5e-7), branchless
__device__ __forceinline__ u64 gelu2(u64 x) {
    u64 ax = x & 0x7FFFFFFF7FFFFFFFULL;
    u64 z  = f2mul(ax, dup2(0.70710678118654752f));
    u64 den = f2fma(z, dup2(0.3275911f), dup2(1.0f));
    float dl, dh, rl, rh;
    unpk2(den, dl, dh);
    asm("rcp.approx.f32 %0,%1;" : "=f"(rl) : "f"(dl));
    asm("rcp.approx.f32 %0,%1;" : "=f"(rh) : "f"(dh));
    u64 t = pk2(rl, rh);
    u64 z2 = f2mul(z, z);
    u64 m  = f2mul(z2, dup2(-1.4426950408889634f));
    float ml, mh, el, eh;
    unpk2(m, ml, mh);
    asm("ex2.approx.f32 %0,%1;" : "=f"(el) : "f"(ml));
    asm("ex2.approx.f32 %0,%1;" : "=f"(eh) : "f"(mh));
    u64 e = pk2(el, eh);
    u64 p = f2fma(t, dup2(1.061405429f), dup2(-1.453152027f));
    p = f2fma(p, t, dup2(1.421413741f));
    p = f2fma(p, t, dup2(-0.284496736f));
    p = f2fma(p, t, dup2(0.254829592f));
    p = f2mul(p, t);
    u64 np = p ^ 0x8000000080000000ULL;
    u64 u  = f2fma(np, e, dup2(1.0f));
    u64 E  = u | (x & 0x8000000080000000ULL);
    u64 h  = f2fma(E, dup2(0.5f), dup2(0.5f));
    return f2mul(x, h);
}

// scratch
__device__ float g_f0[VARS * N_PTS * 32];
__device__ float g_acc[VARS * N_PTS * 32];

// ---------------------------------------------------------------------------
// Projection MLP: per (var,point): 8 -> gelu 64 -> 32. One warp per (var,pt).
// ---------------------------------------------------------------------------
__global__ void proj_kernel(const float* __restrict__ inp,
                            const float* __restrict__ W0, const float* __restrict__ b0,
                            const float* __restrict__ W1, const float* __restrict__ b1,
                            float* __restrict__ f0) {
    __shared__ float hs[4][64];
    int warp = threadIdx.x >> 5, lane = threadIdx.x & 31;
    int pv = blockIdx.x * 4 + warp;
    if (pv >= VARS * N_PTS) return;
    int v = pv / N_PTS, n = pv - v * N_PTS;
    const float* x = inp + n * (VARS * 8) + v * 8;
    float xr[8];
#pragma unroll
    for (int i = 0; i < 8; i++) xr[i] = x[i];
    float a0 = b0[lane], a1 = b0[lane + 32];
#pragma unroll
    for (int i = 0; i < 8; i++) {
        a0 = fmaf(xr[i], W0[i * 64 + lane], a0);
        a1 = fmaf(xr[i], W0[i * 64 + lane + 32], a1);
    }
    hs[warp][lane]      = gelu(a0);
    hs[warp][lane + 32] = gelu(a1);
    __syncwarp();
    float acc = b1[lane];
#pragma unroll
    for (int h = 0; h < 64; h++) acc = fmaf(hs[warp][h], W1[h * 32 + lane], acc);
    f0[(size_t)pv * 32 + lane] = acc;
}

// ---------------------------------------------------------------------------
// Block-GEMM edge MLP: tile of 64 edges per block, 256 threads =
// 32 edge-rows x 8 neuron-groups. Thread computes 2 edges x 10 neurons
// (5 packed u64 accumulators per edge). Activations flow through shared
// (X[36][64] floats, H1/H2[40][64] packed u64), weights broadcast from
// shared. FMA2 : LDS-wavefront ratio ~6:1 -> FMA-pipe bound.
// ---------------------------------------------------------------------------
#define TPB 256

// shared layout (float offsets)
#define SO_W0   0        // 2880
#define SO_W1   2880     // 6400
#define SO_W2   9280     // 2560
#define SO_B0   11840    // 80
#define SO_B1   11920    // 80
#define SO_B2   12000    // 32 (+16 pad)
#define SO_X    12048    // 36*64 = 2304
#define SO_H1   14352    // u64[40*64] = 5120 floats (byte off 57408, 8B aligned)
#define SO_H2   19472    // 5120
#define SO_SEG  24592    // 64 ints
#define SO_JN   24656    // 64 ints
#define SM_FLOATS 24720  // 98,880 B

template <int MODE>
__global__ void __launch_bounds__(TPB, 2)
edge_kernel(const float* __restrict__ Wa, const float* __restrict__ ba,
            const float* __restrict__ Wb, const float* __restrict__ bb,
            const float* __restrict__ Wc, const float* __restrict__ bc,
            const float* __restrict__ grid_in, const float* __restrict__ grid_out,
            const float* __restrict__ fsrc,
            const int* __restrict__ idxA, const int* __restrict__ idxB,
            float* __restrict__ outbuf, int E) {
    extern __shared__ float sm[];
    float* W0s = sm + SO_W0;
    float* W1s = sm + SO_W1;
    float* W2s = sm + SO_W2;
    float* b0s = sm + SO_B0;
    float* b1s = sm + SO_B1;
    float* b2s = sm + SO_B2;
    float* Xs  = sm + SO_X;
    u64*   H1u = (u64*)(sm + SO_H1);
    u64*   H2u = (u64*)(sm + SO_H2);
    int*   seg_sh = (int*)(sm + SO_SEG);
    int*   jn_sh  = (int*)(sm + SO_JN);

    int tid = threadIdx.x;
    int v = blockIdx.y;
    int e0 = blockIdx.x * 64;

    // ---- stage weights ----
    for (int i = tid; i < 2880; i += TPB) W0s[i] = Wa[i];
    for (int i = tid; i < 6400; i += TPB) W1s[i] = Wb[i];
    for (int i = tid; i < 2560; i += TPB) W2s[i] = Wc[i];
    if (tid < 80) { b0s[tid] = ba[tid]; b1s[tid] = bb[tid]; }
    if (tid < 32) b2s[tid] = bc[tid];

    // ---- gather A: indices + positions (threads 0..63) ----
    if (tid < 64) {
        int e = e0 + tid;
        int valid = e < E;
        int jn = 0, sg = -1;
        if (valid) {
            jn = idxA[e];
            sg = (MODE == 0) ? idxB[e] : e / K_LAST;
        }
        jn_sh[tid] = jn;
        seg_sh[tid] = sg;
        float p0 = 0, p1 = 0, p2 = 0, p3 = 0;
        if (valid) {
            p0 = grid_in[2 * jn]; p1 = grid_in[2 * jn + 1];
            if (MODE == 0) { p2 = grid_in[2 * sg];  p3 = grid_in[2 * sg + 1]; }
            else           { p2 = grid_out[2 * sg]; p3 = grid_out[2 * sg + 1]; }
        }
        Xs[0 * 64 + tid] = p0; Xs[1 * 64 + tid] = p1;
        Xs[2 * 64 + tid] = p2; Xs[3 * 64 + tid] = p3;
    }
    __syncthreads();

    // ---- gather B: f-vectors, 4 threads per edge (8 floats each) ----
    {
        int el = tid & 63, q = tid >> 6;
        int sg = seg_sh[el];
        float4 t0 = make_float4(0.f, 0.f, 0.f, 0.f), t1 = t0;
        if (sg >= 0) {
            const float4* fp = (const float4*)(fsrc + ((size_t)v * N_PTS + jn_sh[el]) * 32 + q * 8);
            t0 = fp[0]; t1 = fp[1];
        }
        int ib = 4 + q * 8;
        Xs[(ib + 0) * 64 + el] = t0.x; Xs[(ib + 1) * 64 + el] = t0.y;
        Xs[(ib + 2) * 64 + el] = t0.z; Xs[(ib + 3) * 64 + el] = t0.w;
        Xs[(ib + 4) * 64 + el] = t1.x; Xs[(ib + 5) * 64 + el] = t1.y;
        Xs[(ib + 6) * 64 + el] = t1.z; Xs[(ib + 7) * 64 + el] = t1.w;
    }
    __syncthreads();

    int r = tid & 31;        // edge row (edges r and r+32)
    int c = tid >> 5;        // neuron group (10 neurons: c*10 .. c*10+9)

    u64 acc0[5], acc1[5];

    // ---- layer 1: K=36 ----
    {
        const float* bp = b0s + c * 10;
#pragma unroll
        for (int j = 0; j < 5; j++) {
            u64 b = *(const u64*)(bp + 2 * j);
            acc0[j] = b; acc1[j] = b;
        }
#pragma unroll 4
        for (int k = 0; k < 36; k++) {
            float x0 = Xs[k * 64 + r];
            float x1 = Xs[k * 64 + r + 32];
            u64 d0 = dup2(x0), d1 = dup2(x1);
            const float* wr = W0s + k * 80 + c * 10;
#pragma unroll
            for (int j = 0; j < 5; j++) {
                u64 w = *(const u64*)(wr + 2 * j);
                acc0[j] = f2fma(d0, w, acc0[j]);
                acc1[j] = f2fma(d1, w, acc1[j]);
            }
        }
#pragma unroll
        for (int j = 0; j < 5; j++) {
            H1u[(c * 5 + j) * 64 + r]      = gelu2(acc0[j]);
            H1u[(c * 5 + j) * 64 + r + 32] = gelu2(acc1[j]);
        }
    }
    __syncthreads();

    // ---- layer 2: K=80 (read packed h pairs) ----
    {
        const float* bp = b1s + c * 10;
#pragma unroll
        for (int j = 0; j < 5; j++) {
            u64 b = *(const u64*)(bp + 2 * j);
            acc0[j] = b; acc1[j] = b;
        }
#pragma unroll 4
        for (int p = 0; p < 40; p++) {
            u64 h0 = H1u[p * 64 + r];
            u64 h1 = H1u[p * 64 + r + 32];
            float h0a, h0b, h1a, h1b;
            unpk2(h0, h0a, h0b); unpk2(h1, h1a, h1b);
            u64 d0a = dup2(h0a), d0b = dup2(h0b);
            u64 d1a = dup2(h1a), d1b = dup2(h1b);
            const float* wr0 = W1s + (2 * p) * 80 + c * 10;
            const float* wr1 = wr0 + 80;
#pragma unroll
            for (int j = 0; j < 5; j++) {
                u64 wA = *(const u64*)(wr0 + 2 * j);
                u64 wB = *(const u64*)(wr1 + 2 * j);
                acc0[j] = f2fma(d0a, wA, acc0[j]);
                acc0[j] = f2fma(d0b, wB, acc0[j]);
                acc1[j] = f2fma(d1a, wA, acc1[j]);
                acc1[j] = f2fma(d1b, wB, acc1[j]);
            }
        }
#pragma unroll
        for (int j = 0; j < 5; j++) {
            H2u[(c * 5 + j) * 64 + r]      = gelu2(acc0[j]);
            H2u[(c * 5 + j) * 64 + r + 32] = gelu2(acc1[j]);
        }
    }
    __syncthreads();

    // ---- layer 3: K=80, N=32 (thread: 2 edges x 4 neurons = 2 u64 each) ----
    u64 o00, o01, o10, o11;
    {
        o00 = *(const u64*)(b2s + c * 4);
        o01 = *(const u64*)(b2s + c * 4 + 2);
        o10 = o00; o11 = o01;
#pragma unroll 4
        for (int p = 0; p < 40; p++) {
            u64 h0 = H2u[p * 64 + r];
            u64 h1 = H2u[p * 64 + r + 32];
            float h0a, h0b, h1a, h1b;
            unpk2(h0, h0a, h0b); unpk2(h1, h1a, h1b);
            u64 d0a = dup2(h0a), d0b = dup2(h0b);
            u64 d1a = dup2(h1a), d1b = dup2(h1b);
            const float* w20 = W2s + (2 * p) * 32 + c * 4;
            const float* w21 = w20 + 32;
            u64 wa0 = *(const u64*)(w20),     wa1 = *(const u64*)(w20 + 2);
            u64 wb0 = *(const u64*)(w21),     wb1 = *(const u64*)(w21 + 2);
            o00 = f2fma(d0a, wa0, o00); o01 = f2fma(d0a, wa1, o01);
            o00 = f2fma(d0b, wb0, o00); o01 = f2fma(d0b, wb1, o01);
            o10 = f2fma(d1a, wa0, o10); o11 = f2fma(d1a, wa1, o11);
            o10 = f2fma(d1b, wb0, o10); o11 = f2fma(d1b, wb1, o11);
        }
    }

    // ---- scatter ----
#pragma unroll
    for (int e2 = 0; e2 < 2; e2++) {
        int sg = seg_sh[r + 32 * e2];
        if (sg < 0) continue;
        u64 oa = e2 ? o10 : o00;
        u64 ob = e2 ? o11 : o01;
        float f0a, f0b, f1a, f1b;
        unpk2(oa, f0a, f0b); unpk2(ob, f1a, f1b);
        float* dst;
        if (MODE == 0) {
            dst = outbuf + ((size_t)v * N_PTS + sg) * 32 + c * 4;
        } else {
            dst = outbuf + (size_t)sg * (VARS * 32) + v * 32 + c * 4;
            f0a *= 0.1f; f0b *= 0.1f; f1a *= 0.1f; f1b *= 0.1f;
        }
        atomicAdd(dst + 0, f0a);
        atomicAdd(dst + 1, f0b);
        atomicAdd(dst + 2, f1a);
        atomicAdd(dst + 3, f1b);
    }
}

// f1 = segment_sum * inv_count + f0 (in place into f0)
__global__ void f1_kernel(float* __restrict__ f0, const float* __restrict__ acc,
                          const int* __restrict__ counts) {
    int idx = blockIdx.x * 256 + threadIdx.x;
    if (idx >= VARS * N_PTS * 32) return;
    int n = (idx >> 5) % N_PTS;
    int cnt = counts[n];
    float inv = 1.0f / (float)(cnt > 1 ? cnt : 1);
    f0[idx] = fmaf(acc[idx], inv, f0[idx]);
}

extern "C" void kernel_launch(void* const* d_in, const int* in_sizes, int n_in,
                              void* d_out, int out_size) {
    const float* inp   = (const float*)d_in[0];
    const float* gin   = (const float*)d_in[1];
    const float* gout  = (const float*)d_in[2];
    const float* pW0   = (const float*)d_in[3];
    const float* pb0   = (const float*)d_in[4];
    const float* pW1   = (const float*)d_in[5];
    const float* pb1   = (const float*)d_in[6];
    const float* i0W0  = (const float*)d_in[7];
    const float* i0b0  = (const float*)d_in[8];
    const float* i0W1  = (const float*)d_in[9];
    const float* i0b1  = (const float*)d_in[10];
    const float* i0W2  = (const float*)d_in[11];
    const float* i0b2  = (const float*)d_in[12];
    const float* i1W0  = (const float*)d_in[13];
    const float* i1b0  = (const float*)d_in[14];
    const float* i1W1  = (const float*)d_in[15];
    const float* i1b1  = (const float*)d_in[16];
    const float* i1W2  = (const float*)d_in[17];
    const float* i1b2  = (const float*)d_in[18];
    const int* nbr_index  = (const int*)d_in[19];
    const int* nbr_seg    = (const int*)d_in[20];
    const int* nbr_counts = (const int*)d_in[21];
    const int* nbr_last   = (const int*)d_in[22];
    int E = in_sizes[19];

    float *f0, *acc;
    cudaGetSymbolAddress((void**)&f0,  g_f0);
    cudaGetSymbolAddress((void**)&acc, g_acc);

    cudaMemsetAsync(acc, 0, sizeof(float) * VARS * N_PTS * 32);
    cudaMemsetAsync(d_out, 0, sizeof(float) * (size_t)out_size);

    proj_kernel<<<(VARS * N_PTS + 3) / 4, 128>>>(inp, pW0, pb0, pW1, pb1, f0);

    const int SMEM = SM_FLOATS * (int)sizeof(float);  // 98,880 B
    cudaFuncSetAttribute(edge_kernel<0>, cudaFuncAttributeMaxDynamicSharedMemorySize, SMEM);
    cudaFuncSetAttribute(edge_kernel<1>, cudaFuncAttributeMaxDynamicSharedMemorySize, SMEM);

    dim3 g1((unsigned)((E + 63) / 64), VARS);
    edge_kernel<0><<<g1, TPB, SMEM>>>(i0W0, i0b0, i0W1, i0b1, i0W2, i0b2,
                                      gin, nullptr, f0, nbr_index, nbr_seg, acc, E);

    f1_kernel<<<(VARS * N_PTS * 32 + 255) / 256, 256>>>(f0, acc, nbr_counts);

    int E2 = M_PTS * K_LAST;
    dim3 g2((unsigned)((E2 + 63) / 64), VARS);
    edge_kernel<1><<<g2, TPB, SMEM>>>(i1W0, i1b0, i1W1, i1b1, i1W2, i1b2,
                                      gin, gout, f0, nbr_last, nullptr, (float*)d_out, E2);
}